// round 14
// baseline (speedup 1.0000x reference)
#include <cuda_runtime.h>
#include <cuda_fp16.h>
#include <cstdint>

// Problem constants
#define NN 1024   // nodes
#define NB 8      // batch
#define NS 64     // timesteps
#define NH 32     // hidden

// GEMM tiling: per CTA, M=128 (n rows) x N=256 cols (2u x 64t x 2 gates), K=1024
#define NKT 16           // k-iters (chunks of 64)
#define AP 80            // smem halfs per A row -> conflict-free LDS.64
#define BP 80            // smem halfs per B col
#define ACHUNK (128 * 64)      // g_A halfs per chunk? no: padded!
// g_A keeps the PADDED layout (global == smem, linear cp.async — proven fastest)
#define ACHUNK_P (128 * AP)    // 10240 halfs
#define ABYTES (ACHUNK_P * 2)  // 20480 B per A stage
#define BBYTES (256 * BP * 2)  // 40960 B per B buf
#define XHBYTES 8192           // 64 t x 32 half2 per chunk
#define OFF_W   0              // 4 x 1024 halfs = 8192 B
#define OFF_XH  8192           // 3 stages x 8192 = 24576
#define OFF_A   32768          // 4 stages x 20480 = 81920
#define OFF_B   114688         // 2 bufs x 40960 = 81920
#define SMEM_BYTES 196608      // Z epilogue (131584) aliases from 0
#define ZPITCH 257

// Precomputed buffers
__device__ __align__(16) __half g_A[(size_t)NB * 8 * NKT * ACHUNK_P];  // ~21 MB
__device__ __align__(16) __half2 g_xh[(size_t)NB * NS * (NN / 2)];     // xh[b][t][m/2]
__device__ __align__(16) float  g_h[NB * NN * NH];

// ---------------- helpers ----------------
__device__ __forceinline__ uint32_t smem_u32(const void* p) {
    uint32_t a;
    asm("{ .reg .u64 t; cvta.to.shared.u64 t, %1; cvt.u32.u64 %0, t; }" : "=r"(a) : "l"(p));
    return a;
}
__device__ __forceinline__ void cp16(uint32_t s, const void* g) {
    asm volatile("cp.async.cg.shared.global [%0], [%1], 16;" :: "r"(s), "l"(g) : "memory");
}
__device__ __forceinline__ void cp_commit() {
    asm volatile("cp.async.commit_group;" ::: "memory");
}
template <int N>
__device__ __forceinline__ void cp_wait() {
    asm volatile("cp.async.wait_group %0;" :: "n"(N) : "memory");
}
__device__ __forceinline__ void mma_f16(float c[4], uint2 alo, uint2 ahi, uint2 bf) {
    asm volatile(
        "mma.sync.aligned.m16n8k16.row.col.f32.f16.f16.f32 "
        "{%0,%1,%2,%3}, {%4,%5,%6,%7}, {%8,%9}, {%0,%1,%2,%3};\n"
        : "+f"(c[0]), "+f"(c[1]), "+f"(c[2]), "+f"(c[3])
        : "r"(alo.x), "r"(ahi.x), "r"(alo.y), "r"(ahi.y), "r"(bf.x), "r"(bf.y));
}
__device__ __forceinline__ uint32_t pack2(float a, float b) {
    __half2 h = __halves2half2(__float2half_rn(a), __float2half_rn(b));
    return *reinterpret_cast<uint32_t*>(&h);
}
__device__ __forceinline__ uint32_t hmul2u(uint32_t a, uint32_t b) {
    __half2 v = __hmul2(*reinterpret_cast<__half2*>(&a), *reinterpret_cast<__half2*>(&b));
    return *reinterpret_cast<uint32_t*>(&v);
}

// ---------------- prep: xh[b][t][m/2] via coalesced smem transpose ----------------
#define XTP 68
__global__ void __launch_bounds__(256)
xh_kernel(const float* __restrict__ X) {
    __shared__ float s[64 * XTP];
    const int tid  = threadIdx.x;
    const int mblk = blockIdx.x & 15;
    const int b    = blockIdx.x >> 4;

    const float* src = X + (size_t)b * NN * NS + (size_t)(mblk * 64) * NS;
#pragma unroll
    for (int i = 0; i < 4; i++) {
        int slot = tid + i * 256;
        int row = slot >> 4, j = slot & 15;
        *(float4*)(s + row * XTP + j * 4) = *(const float4*)(src + (size_t)row * NS + j * 4);
    }
    __syncthreads();

    const int t = tid >> 2;
    const int g = tid & 3;
    uint32_t r[8];
#pragma unroll
    for (int i = 0; i < 8; i++) {
        int ml = 8 * g + i;
        r[i] = pack2(s[(2 * ml) * XTP + t], s[(2 * ml + 1) * XTP + t]);
    }
    uint32_t* dst = (uint32_t*)(g_xh + (size_t)(b * NS + t) * 512 + mblk * 32 + 8 * g);
    *(uint4*)(dst)     = make_uint4(r[0], r[1], r[2], r[3]);
    *(uint4*)(dst + 4) = make_uint4(r[4], r[5], r[6], r[7]);
}

// ---------------- prep: A = half(G), fragment-permuted, padded rows ----------------
__global__ void __launch_bounds__(256)
prepA_kernel(const float* __restrict__ G) {
    int idx = blockIdx.x * 256 + threadIdx.x;   // 2,097,152 quads
    int q   = idx & 3;
    int ks  = (idx >> 2) & 3;
    int row = (idx >> 4) & 127;
    int kt  = (idx >> 11) & 15;
    int mt  = (idx >> 15) & 7;
    int b   = idx >> 18;
    const float* src = G + ((size_t)b * NN + mt * 128 + row) * NN + kt * 64 + ks * 16 + 2 * q;
    uint2 v;
    v.x = pack2(src[0], src[1]);
    v.y = pack2(src[8], src[9]);
    *reinterpret_cast<uint2*>(
        g_A + (size_t)((b * 8 + mt) * 16 + kt) * ACHUNK_P + row * AP + ks * 16 + q * 4) = v;
}

// ---------------- main: fp16 HMMA GEMM with in-kernel B production + fused GRU ----------------
__global__ void __launch_bounds__(256, 1)
gemm_gru_kernel(const float* __restrict__ Wu, const float* __restrict__ bu,
                const float* __restrict__ Wc, const float* __restrict__ bc,
                const float* __restrict__ h0)
{
    extern __shared__ __align__(16) char smem[];
    const uint32_t sb = smem_u32(smem);

    const int tid  = threadIdx.x;
    const int wid  = tid >> 5;
    const int lane = tid & 31;
    const int wm   = wid >> 2;
    const int wn   = wid & 3;
    const int grp  = lane >> 2;
    const int qid  = lane & 3;

    const int mt = blockIdx.x;
    const int nt = blockIdx.y;
    const int b  = blockIdx.z;
    const int u0 = nt * 2;

    const __half* Asrc = g_A + (size_t)((b * 8 + mt) * 16) * ACHUNK_P;
    const char*   Xsrc = (const char*)(g_xh + (size_t)(b * NS) * 512);

    // ---- prologue: stage 4 weight rows (u0,u0+1 x u/c gates) as half2 into smem ----
    {
        int widx = tid >> 6;               // 0..3 = gate*2 + ul
        int gate = widx >> 1, ul = widx & 1;
        int j = (tid & 63) * 16;
        const float* wsrc = (gate ? Wc : Wu) + (size_t)(u0 + ul) * NN + j;
        float4 f0 = *(const float4*)(wsrc + 0);
        float4 f1 = *(const float4*)(wsrc + 4);
        float4 f2 = *(const float4*)(wsrc + 8);
        float4 f3 = *(const float4*)(wsrc + 12);
        uint4 o0 = make_uint4(pack2(f0.x, f0.y), pack2(f0.z, f0.w),
                              pack2(f1.x, f1.y), pack2(f1.z, f1.w));
        uint4 o1 = make_uint4(pack2(f2.x, f2.y), pack2(f2.z, f2.w),
                              pack2(f3.x, f3.y), pack2(f3.z, f3.w));
        *(uint4*)(smem + OFF_W + (widx * 1024 + j) * 2)      = o0;
        *(uint4*)(smem + OFF_W + (widx * 1024 + j) * 2 + 16) = o1;
    }

    float acc[4][8][4];
#pragma unroll
    for (int i = 0; i < 4; i++)
#pragma unroll
        for (int j = 0; j < 8; j++)
#pragma unroll
            for (int r = 0; r < 4; r++) acc[i][j][r] = 0.f;

// cp.async group J: A chunk J (linear, padded) + xh chunk J (row-gathered)
#define ISSUE_GRP(J) do {                                                          \
    uint32_t sa = sb + OFF_A + ((J) & 3) * ABYTES;                                 \
    const char* ga = (const char*)(Asrc + (size_t)(J) * ACHUNK_P);                 \
    _Pragma("unroll")                                                              \
    for (int i = 0; i < 5; i++)                                                    \
        cp16(sa + tid * 16 + i * 4096, ga + tid * 16 + i * 4096);                  \
    uint32_t sx = sb + OFF_XH + ((J) % 3) * XHBYTES;                               \
    _Pragma("unroll")                                                              \
    for (int i = 0; i < 2; i++) {                                                  \
        int slot = tid + i * 256;    /* 512 slots: t<64, j<8 */                    \
        int t = slot >> 3, j = slot & 7;                                           \
        cp16(sx + t * 128 + j * 16,                                                \
             Xsrc + ((size_t)t * 512 + (J) * 32) * 4 + j * 16);                    \
    }                                                                              \
    cp_commit();                                                                   \
} while (0)

// Produce B chunk KT1 into buf (KT1&1): B[col,k] = wsm[u_g,k] * xh[k,t]
#define CONVERT(KT1) do {                                                          \
    const int xs_ = ((KT1) % 3);                                                   \
    char* bbuf = smem + OFF_B + ((KT1) & 1) * BBYTES;                              \
    _Pragma("unroll")                                                              \
    for (int i = 0; i < 4; i++) {                                                  \
        int unit = tid + i * 256;                                                  \
        int ks = unit & 3, col = unit >> 2;                                        \
        int ul = col >> 7, t = (col & 127) >> 1, gate = col & 1;                   \
        int widx = gate * 2 + ul;                                                  \
        const uint4* wp = (const uint4*)(smem + OFF_W + widx * 2048 +              \
                                         (KT1) * 128 + ks * 32);                   \
        const uint4* xp = (const uint4*)(smem + OFF_XH + xs_ * XHBYTES +           \
                                         t * 128 + ks * 32);                       \
        uint4 w0 = wp[0], w1 = wp[1];                                              \
        uint4 x0 = xp[0], x1 = xp[1];                                              \
        uint32_t r0 = hmul2u(w0.x, x0.x), r1 = hmul2u(w0.y, x0.y);                 \
        uint32_t r2 = hmul2u(w0.z, x0.z), r3 = hmul2u(w0.w, x0.w);                 \
        uint32_t r4 = hmul2u(w1.x, x1.x), r5 = hmul2u(w1.y, x1.y);                 \
        uint32_t r6 = hmul2u(w1.z, x1.z), r7 = hmul2u(w1.w, x1.w);                 \
        uint4* dst = (uint4*)(bbuf + col * (BP * 2) + ks * 32);                    \
        dst[0] = make_uint4(r0, r4, r1, r5);                                       \
        dst[1] = make_uint4(r2, r6, r3, r7);                                       \
    }                                                                              \
} while (0)

#define COMPUTE(KT) do {                                                           \
    const __half* Ab = (const __half*)(smem + OFF_A + ((KT) & 3) * ABYTES);        \
    const __half* Bb = (const __half*)(smem + OFF_B + ((KT) & 1) * BBYTES);        \
    _Pragma("unroll")                                                              \
    for (int ks = 0; ks < 4; ks++) {                                               \
        uint2 alo[4], ahi[4], bf[8];                                               \
        _Pragma("unroll")                                                          \
        for (int mi = 0; mi < 4; mi++) {                                           \
            const __half* ap = Ab + (wm * 64 + mi * 16 + grp) * AP + ks * 16 + qid * 4; \
            alo[mi] = *reinterpret_cast<const uint2*>(ap);                         \
            ahi[mi] = *reinterpret_cast<const uint2*>(ap + 8 * AP);                \
        }                                                                          \
        _Pragma("unroll")                                                          \
        for (int nj = 0; nj < 8; nj++)                                             \
            bf[nj] = *reinterpret_cast<const uint2*>(                              \
                Bb + (wn * 64 + nj * 8 + grp) * BP + ks * 16 + qid * 4);           \
        _Pragma("unroll")                                                          \
        for (int mi = 0; mi < 4; mi++)                                             \
        _Pragma("unroll")                                                          \
        for (int nj = 0; nj < 8; nj++)                                             \
            mma_f16(acc[mi][nj], alo[mi], ahi[mi], bf[nj]);                        \
    }                                                                              \
} while (0)

    // Prologue: groups 0,1,2 in flight
    ISSUE_GRP(0);
    ISSUE_GRP(1);
    ISSUE_GRP(2);
    cp_wait<2>();
    __syncthreads();        // group0 (A0, xh0) + w staging published
    CONVERT(0);             // B(0) from xh(0)
    cp_wait<1>();
    __syncthreads();        // group1 (A1, xh1) + B(0) published
    // invariant at iter kt top: B(kt), A(kt), xh(kt+1) published; group kt+2 in flight

#pragma unroll 1
    for (int kt = 0; kt < NKT; kt++) {
        if (kt + 3 < NKT) ISSUE_GRP(kt + 3);
        if (kt + 1 < NKT) CONVERT(kt + 1);
        COMPUTE(kt);
        if (kt + 3 < NKT)      { cp_wait<1>(); __syncthreads(); }
        else if (kt + 1 < NKT) { cp_wait<0>(); __syncthreads(); }
    }
    __syncthreads();   // all COMPUTE done before Z aliases staging smem

    // ---- Epilogue: dump Z to smem, run the GRU recurrence over t ----
    float* Zs = (float*)smem;   // [128][ZPITCH]
#pragma unroll
    for (int mi = 0; mi < 4; mi++)
#pragma unroll
        for (int nj = 0; nj < 8; nj++)
#pragma unroll
            for (int r = 0; r < 4; r++) {
                int row = wm * 64 + mi * 16 + grp + ((r >> 1) ? 8 : 0);
                int col = wn * 64 + nj * 8 + qid * 2 + (r & 1);
                Zs[row * ZPITCH + col] = acc[mi][nj][r];
            }
    __syncthreads();

    {
        const int row = tid & 127;
        const int ul  = tid >> 7;
        const int n   = mt * 128 + row;
        const int u   = u0 + ul;
        float h = h0[(size_t)u * NN + n];
        const float buv = bu[u];
        const float bcv = bc[u];
        const float* zrow = Zs + row * ZPITCH + ul * 128;
#pragma unroll 1
        for (int t = 0; t < NS; t++) {
            float zu = zrow[2 * t]     + buv;
            float zc = zrow[2 * t + 1] + bcv;
            float ug = 1.f / (1.f + __expf(-zu));
            float cg = tanhf(zc);
            h = fmaf(ug, h - cg, cg);
        }
        g_h[((size_t)b * NN + n) * NH + u] = h;
    }
#undef ISSUE_GRP
#undef CONVERT
#undef COMPUTE
}

// ---------------- prediction head (1024-thread blocks) ----------------
#define W1T_PITCH 33
__global__ void __launch_bounds__(1024)
head_kernel(const float* __restrict__ W1, const float* __restrict__ b1,
            const float* __restrict__ W2, const float* __restrict__ b2,
            const float* __restrict__ Wd, const float* __restrict__ bd,
            float* __restrict__ out)
{
    __shared__ float w1t[NH * W1T_PITCH];
    __shared__ float w2t[2 * NH * W1T_PITCH];
    __shared__ float b1s[NH], b2s[NH];

    const int tid = threadIdx.x;
    for (int i = tid; i < NH * NH; i += 1024) {
        int u = i >> 5, k = i & 31;
        w1t[k * W1T_PITCH + u] = W1[i];
    }
    for (int i = tid; i < NH * 2 * NH; i += 1024) {
        int u = i >> 6, k = i & 63;
        w2t[k * W1T_PITCH + u] = W2[i];
    }
    if (tid < NH) { b1s[tid] = b1[tid]; b2s[tid] = b2[tid]; }
    __syncthreads();

    const int warp = blockIdx.x * 32 + (tid >> 5);
    const int lane = tid & 31;
    const int b = warp >> 10;
    const int n = warp & (NN - 1);

    const float hv = g_h[((size_t)b * NN + n) * NH + lane];

    float p0 = 0.f, p1 = 0.f, p2 = 0.f, p3 = 0.f;
#pragma unroll
    for (int k = 0; k < NH; k += 4) {
        p0 = fmaf(w1t[(k + 0) * W1T_PITCH + lane], __shfl_sync(0xffffffffu, hv, k + 0), p0);
        p1 = fmaf(w1t[(k + 1) * W1T_PITCH + lane], __shfl_sync(0xffffffffu, hv, k + 1), p1);
        p2 = fmaf(w1t[(k + 2) * W1T_PITCH + lane], __shfl_sync(0xffffffffu, hv, k + 2), p2);
        p3 = fmaf(w1t[(k + 3) * W1T_PITCH + lane], __shfl_sync(0xffffffffu, hv, k + 3), p3);
    }
    float x1 = b1s[lane] + ((p0 + p1) + (p2 + p3));
    x1 = x1 >= 0.f ? x1 : 0.01f * x1;

    float q0 = 0.f, q1 = 0.f, q2 = 0.f, q3 = 0.f;
#pragma unroll
    for (int k = 0; k < NH; k += 4) {
        q0 = fmaf(w2t[(k + 0) * W1T_PITCH + lane], __shfl_sync(0xffffffffu, x1, k + 0), q0);
        q1 = fmaf(w2t[(k + 1) * W1T_PITCH + lane], __shfl_sync(0xffffffffu, x1, k + 1), q1);
        q2 = fmaf(w2t[(k + 2) * W1T_PITCH + lane], __shfl_sync(0xffffffffu, x1, k + 2), q2);
        q3 = fmaf(w2t[(k + 3) * W1T_PITCH + lane], __shfl_sync(0xffffffffu, x1, k + 3), q3);
    }
#pragma unroll
    for (int k = 0; k < NH; k += 4) {
        q0 = fmaf(w2t[(NH + k + 0) * W1T_PITCH + lane], __shfl_sync(0xffffffffu, hv, k + 0), q0);
        q1 = fmaf(w2t[(NH + k + 1) * W1T_PITCH + lane], __shfl_sync(0xffffffffu, hv, k + 1), q1);
        q2 = fmaf(w2t[(NH + k + 2) * W1T_PITCH + lane], __shfl_sync(0xffffffffu, hv, k + 2), q2);
        q3 = fmaf(w2t[(NH + k + 3) * W1T_PITCH + lane], __shfl_sync(0xffffffffu, hv, k + 3), q3);
    }
    float x2 = b2s[lane] + ((q0 + q1) + (q2 + q3));
    x2 = x2 >= 0.f ? x2 : 0.01f * x2;

    float v = Wd[(size_t)n * 2 * NH + lane] * x2
            + Wd[(size_t)n * 2 * NH + NH + lane] * hv;
#pragma unroll
    for (int o = 16; o; o >>= 1) v += __shfl_xor_sync(0xffffffffu, v, o);
    if (lane == 0) out[(size_t)b * NN + n] = v + bd[n];
}

extern "C" void kernel_launch(void* const* d_in, const int* in_sizes, int n_in,
                              void* d_out, int out_size)
{
    (void)in_sizes; (void)n_in; (void)out_size;
    const float* x  = (const float*)d_in[0];
    const float* g  = (const float*)d_in[2];
    const float* Wu = (const float*)d_in[5];
    const float* bu = (const float*)d_in[6];
    const float* Wc = (const float*)d_in[7];
    const float* bc = (const float*)d_in[8];
    const float* h0 = (const float*)d_in[9];
    const float* W1 = (const float*)d_in[10];
    const float* b1 = (const float*)d_in[11];
    const float* W2 = (const float*)d_in[12];
    const float* b2 = (const float*)d_in[13];
    const float* Wd = (const float*)d_in[14];
    const float* bd = (const float*)d_in[15];
    float* out = (float*)d_out;

    xh_kernel<<<NB * 16, 256>>>(x);
    prepA_kernel<<<8192, 256>>>(g);

    cudaFuncSetAttribute(gemm_gru_kernel,
                         cudaFuncAttributeMaxDynamicSharedMemorySize, SMEM_BYTES);
    dim3 grid(8, 16, NB);
    gemm_gru_kernel<<<grid, 256, SMEM_BYTES>>>(Wu, bu, Wc, bc, h0);

    head_kernel<<<(NB * NN) / 32, 1024>>>(W1, b1, W2, b2, Wd, bd, out);
}

// round 15
// speedup vs baseline: 1.1214x; 1.1214x over previous
#include <cuda_runtime.h>
#include <cuda_fp16.h>
#include <cstdint>

// Problem constants
#define NN 1024   // nodes
#define NB 8      // batch
#define NS 64     // timesteps
#define NH 32     // hidden

// GEMM tiling: per CTA, M=128 (n rows) x N=256 cols (2u x 64t x 2 gates), K=1024
#define BK 64
#define NKT 16           // k-iters
#define STAGES 3
#define AP 80            // halfs per A row (64 data + 16 pad) -> conflict-free LDS.64
#define BP 80            // halfs per B col
#define ACHUNK (128 * AP)   // 10240 halfs per (tile, kchunk)
#define BCHUNK (256 * BP)   // 20480
#define ABYTES (ACHUNK * 2) // 20480 B
#define BBYTES (BCHUNK * 2) // 40960 B
#define SBYTES (ABYTES + BBYTES)        // 61440 per stage
#define ZPITCH 257
#define SMEM_BYTES (STAGES * SBYTES)    // 184320; Z tile (131584) aliases this

// Precomputed operand buffers (16B-aligned; padded rows, global layout == smem layout)
__device__ __align__(16) __half g_A[(size_t)NB * 8 * NKT * ACHUNK];    // ~21 MB
__device__ __align__(16) __half g_B[(size_t)NB * 16 * NKT * BCHUNK];   // ~84 MB
__device__ __align__(16) __half2 g_xh[(size_t)NB * NS * (NN / 2)];     // xh[b][t][m/2]
__device__ __align__(16) float  g_h[NB * NN * NH];

// ---------------- helpers ----------------
__device__ __forceinline__ uint32_t smem_u32(const void* p) {
    uint32_t a;
    asm("{ .reg .u64 t; cvta.to.shared.u64 t, %1; cvt.u32.u64 %0, t; }" : "=r"(a) : "l"(p));
    return a;
}
__device__ __forceinline__ void cp16(uint32_t s, const void* g) {
    asm volatile("cp.async.cg.shared.global [%0], [%1], 16;" :: "r"(s), "l"(g) : "memory");
}
__device__ __forceinline__ void cp_commit() {
    asm volatile("cp.async.commit_group;" ::: "memory");
}
template <int N>
__device__ __forceinline__ void cp_wait() {
    asm volatile("cp.async.wait_group %0;" :: "n"(N) : "memory");
}
__device__ __forceinline__ void mma_f16(float c[4], uint2 alo, uint2 ahi, uint2 bf) {
    asm volatile(
        "mma.sync.aligned.m16n8k16.row.col.f32.f16.f16.f32 "
        "{%0,%1,%2,%3}, {%4,%5,%6,%7}, {%8,%9}, {%0,%1,%2,%3};\n"
        : "+f"(c[0]), "+f"(c[1]), "+f"(c[2]), "+f"(c[3])
        : "r"(alo.x), "r"(ahi.x), "r"(alo.y), "r"(ahi.y), "r"(bf.x), "r"(bf.y));
}
__device__ __forceinline__ uint32_t pack2(float a, float b) {
    __half2 h = __halves2half2(__float2half_rn(a), __float2half_rn(b));
    return *reinterpret_cast<uint32_t*>(&h);
}

// ---------------- prep: xh[b][t][m/2] via coalesced smem transpose ----------------
#define XTP 68   // 272B rows keep float4 16B-aligned
__global__ void __launch_bounds__(256)
xh_kernel(const float* __restrict__ X) {
    __shared__ float s[64 * XTP];
    const int tid  = threadIdx.x;
    const int mblk = blockIdx.x & 15;
    const int b    = blockIdx.x >> 4;

    const float* src = X + (size_t)b * NN * NS + (size_t)(mblk * 64) * NS;
#pragma unroll
    for (int i = 0; i < 4; i++) {
        int slot = tid + i * 256;
        int row = slot >> 4, j = slot & 15;
        *(float4*)(s + row * XTP + j * 4) = *(const float4*)(src + (size_t)row * NS + j * 4);
    }
    __syncthreads();

    const int t = tid >> 2;
    const int g = tid & 3;
    uint32_t r[8];
#pragma unroll
    for (int i = 0; i < 8; i++) {
        int ml = 8 * g + i;
        r[i] = pack2(s[(2 * ml) * XTP + t], s[(2 * ml + 1) * XTP + t]);
    }
    uint32_t* dst = (uint32_t*)(g_xh + (size_t)(b * NS + t) * 512 + mblk * 32 + 8 * g);
    *(uint4*)(dst)     = make_uint4(r[0], r[1], r[2], r[3]);
    *(uint4*)(dst + 4) = make_uint4(r[4], r[5], r[6], r[7]);
}

// ---------------- fused prep: blocks [0,8192) = B-convert, [8192,16384) = A-convert ----
__global__ void __launch_bounds__(256)
prep_kernel(const float* __restrict__ G,
            const float* __restrict__ Wu, const float* __restrict__ Wc) {
    const int tid = threadIdx.x;
    if (blockIdx.x < 8192) {
        // ---- B: B[col,k] = h(w[k]) * h(x[k,t]), fragment-permuted ----
        int idx = blockIdx.x * 256 + tid;   // 2,097,152
        int ks  = idx & 3;
        int col = (idx >> 2) & 255;
        int kt  = (idx >> 10) & 15;
        int nt  = (idx >> 14) & 15;
        int b   = idx >> 18;
        int ul = col >> 7, t = (col & 127) >> 1, gate = col & 1;
        int u  = nt * 2 + ul;

        const __half2* xp = g_xh + (size_t)(b * NS + t) * 512 + kt * 32 + ks * 8;
        const float*   wf = (gate ? Wc : Wu) + (size_t)u * NN + kt * 64 + ks * 16;

        float4 f0 = *(const float4*)(wf + 0);
        float4 f1 = *(const float4*)(wf + 4);
        float4 f2 = *(const float4*)(wf + 8);
        float4 f3 = *(const float4*)(wf + 12);
        uint32_t w[8];
        w[0] = pack2(f0.x, f0.y); w[1] = pack2(f0.z, f0.w);
        w[2] = pack2(f1.x, f1.y); w[3] = pack2(f1.z, f1.w);
        w[4] = pack2(f2.x, f2.y); w[5] = pack2(f2.z, f2.w);
        w[6] = pack2(f3.x, f3.y); w[7] = pack2(f3.z, f3.w);

        uint32_t r[8];
#pragma unroll
        for (int j = 0; j < 8; j++) {
            __half2 wv = *reinterpret_cast<__half2*>(&w[j]);
            __half2 v  = __hmul2(wv, xp[j]);
            r[j] = *reinterpret_cast<uint32_t*>(&v);
        }
        uint4 o0 = make_uint4(r[0], r[4], r[1], r[5]);
        uint4 o1 = make_uint4(r[2], r[6], r[3], r[7]);
        uint4* dst = reinterpret_cast<uint4*>(
            g_B + (size_t)((b * 16 + nt) * 16 + kt) * BCHUNK + col * BP + ks * 16);
        dst[0] = o0;
        dst[1] = o1;
    } else {
        // ---- A: half(G), fragment-permuted ----
        int idx = (blockIdx.x - 8192) * 256 + tid;   // 2,097,152 quads
        int q   = idx & 3;
        int ks  = (idx >> 2) & 3;
        int row = (idx >> 4) & 127;
        int kt  = (idx >> 11) & 15;
        int mt  = (idx >> 15) & 7;
        int b   = idx >> 18;
        const float* src = G + ((size_t)b * NN + mt * 128 + row) * NN + kt * 64 + ks * 16 + 2 * q;
        uint2 v;
        v.x = pack2(src[0], src[1]);
        v.y = pack2(src[8], src[9]);
        *reinterpret_cast<uint2*>(
            g_A + (size_t)((b * 8 + mt) * 16 + kt) * ACHUNK + row * AP + ks * 16 + q * 4) = v;
    }
}

// ---------------- main: fp16 HMMA GEMM (3-stage cp.async ring) + fused GRU ----------------
__global__ void __launch_bounds__(256, 1)
gemm_gru_kernel(const float* __restrict__ bu, const float* __restrict__ bc,
                const float* __restrict__ h0)
{
    extern __shared__ __align__(16) char smem[];
    const uint32_t sb = smem_u32(smem);

    const int tid  = threadIdx.x;
    const int wid  = tid >> 5;
    const int lane = tid & 31;
    const int wm   = wid >> 2;
    const int wn   = wid & 3;
    const int grp  = lane >> 2;
    const int qid  = lane & 3;

    const int mt = blockIdx.x;
    const int nt = blockIdx.y;
    const int b  = blockIdx.z;

    const __half* Asrc = g_A + (size_t)((b * 8 + mt) * 16) * ACHUNK;
    const __half* Bsrc = g_B + (size_t)((b * 16 + nt) * 16) * BCHUNK;

    float acc[4][8][4];
#pragma unroll
    for (int i = 0; i < 4; i++)
#pragma unroll
        for (int j = 0; j < 8; j++)
#pragma unroll
            for (int r = 0; r < 4; r++) acc[i][j][r] = 0.f;

// Global layout == smem layout: fully linear cp.async (proven fastest)
#define ISSUE(KT, SLOT) do {                                                       \
    uint32_t sa = sb + (SLOT) * SBYTES;                                            \
    const char* ga = (const char*)(Asrc + (size_t)(KT) * ACHUNK);                  \
    _Pragma("unroll")                                                              \
    for (int i = 0; i < 5; i++)                                                    \
        cp16(sa + tid * 16 + i * 4096, ga + tid * 16 + i * 4096);                  \
    uint32_t sB = sa + ABYTES;                                                     \
    const char* gb = (const char*)(Bsrc + (size_t)(KT) * BCHUNK);                  \
    _Pragma("unroll")                                                              \
    for (int i = 0; i < 10; i++)                                                   \
        cp16(sB + tid * 16 + i * 4096, gb + tid * 16 + i * 4096);                  \
    cp_commit();                                                                   \
} while (0)

#define COMPUTE(SLOT) do {                                                         \
    const __half* Ab = (const __half*)(smem + (SLOT) * SBYTES);                    \
    const __half* Bb = (const __half*)(smem + (SLOT) * SBYTES + ABYTES);           \
    _Pragma("unroll")                                                              \
    for (int ks = 0; ks < 4; ks++) {                                               \
        uint2 alo[4], ahi[4], bf[8];                                               \
        _Pragma("unroll")                                                          \
        for (int mi = 0; mi < 4; mi++) {                                           \
            const __half* ap = Ab + (wm * 64 + mi * 16 + grp) * AP + ks * 16 + qid * 4; \
            alo[mi] = *reinterpret_cast<const uint2*>(ap);                         \
            ahi[mi] = *reinterpret_cast<const uint2*>(ap + 8 * AP);                \
        }                                                                          \
        _Pragma("unroll")                                                          \
        for (int nj = 0; nj < 8; nj++)                                             \
            bf[nj] = *reinterpret_cast<const uint2*>(                              \
                Bb + (wn * 64 + nj * 8 + grp) * BP + ks * 16 + qid * 4);           \
        _Pragma("unroll")                                                          \
        for (int mi = 0; mi < 4; mi++)                                             \
        _Pragma("unroll")                                                          \
        for (int nj = 0; nj < 8; nj++)                                             \
            mma_f16(acc[mi][nj], alo[mi], ahi[mi], bf[nj]);                        \
    }                                                                              \
} while (0)

    // Prologue: stages 0 and 1 in flight
    ISSUE(0, 0);
    ISSUE(1, 1);

    int slot = 0;
#pragma unroll 1
    for (int kt = 0; kt < NKT; kt++) {
        if (kt < NKT - 1) cp_wait<1>();
        else              cp_wait<0>();
        __syncthreads();
        if (kt + 2 < NKT) {
            int ns = slot + 2; if (ns >= STAGES) ns -= STAGES;
            ISSUE(kt + 2, ns);
        }
        COMPUTE(slot);
        if (++slot == STAGES) slot = 0;
    }
    __syncthreads();   // all COMPUTE done before Z aliases staging smem

    // ---- Epilogue: dump Z to smem, run the GRU recurrence over t ----
    float* Zs = (float*)smem;   // [128][ZPITCH]
#pragma unroll
    for (int mi = 0; mi < 4; mi++)
#pragma unroll
        for (int nj = 0; nj < 8; nj++)
#pragma unroll
            for (int r = 0; r < 4; r++) {
                int row = wm * 64 + mi * 16 + grp + ((r >> 1) ? 8 : 0);
                int col = wn * 64 + nj * 8 + qid * 2 + (r & 1);
                Zs[row * ZPITCH + col] = acc[mi][nj][r];
            }
    __syncthreads();

    {
        const int row = tid & 127;
        const int ul  = tid >> 7;
        const int n   = mt * 128 + row;
        const int u   = nt * 2 + ul;
        float h = h0[(size_t)u * NN + n];
        const float buv = bu[u];
        const float bcv = bc[u];
        const float* zrow = Zs + row * ZPITCH + ul * 128;
#pragma unroll 1
        for (int t = 0; t < NS; t++) {
            float zu = zrow[2 * t]     + buv;
            float zc = zrow[2 * t + 1] + bcv;
            float ug = 1.f / (1.f + __expf(-zu));
            float cg = tanhf(zc);
            h = fmaf(ug, h - cg, cg);
        }
        g_h[((size_t)b * NN + n) * NH + u] = h;
    }
#undef ISSUE
#undef COMPUTE
}

// ---------------- prediction head (1024-thread blocks) ----------------
#define W1T_PITCH 33
__global__ void __launch_bounds__(1024)
head_kernel(const float* __restrict__ W1, const float* __restrict__ b1,
            const float* __restrict__ W2, const float* __restrict__ b2,
            const float* __restrict__ Wd, const float* __restrict__ bd,
            float* __restrict__ out)
{
    __shared__ float w1t[NH * W1T_PITCH];
    __shared__ float w2t[2 * NH * W1T_PITCH];
    __shared__ float b1s[NH], b2s[NH];

    const int tid = threadIdx.x;
    for (int i = tid; i < NH * NH; i += 1024) {
        int u = i >> 5, k = i & 31;
        w1t[k * W1T_PITCH + u] = W1[i];
    }
    for (int i = tid; i < NH * 2 * NH; i += 1024) {
        int u = i >> 6, k = i & 63;
        w2t[k * W1T_PITCH + u] = W2[i];
    }
    if (tid < NH) { b1s[tid] = b1[tid]; b2s[tid] = b2[tid]; }
    __syncthreads();

    const int warp = blockIdx.x * 32 + (tid >> 5);
    const int lane = tid & 31;
    const int b = warp >> 10;
    const int n = warp & (NN - 1);

    const float hv = g_h[((size_t)b * NN + n) * NH + lane];

    float p0 = 0.f, p1 = 0.f, p2 = 0.f, p3 = 0.f;
#pragma unroll
    for (int k = 0; k < NH; k += 4) {
        p0 = fmaf(w1t[(k + 0) * W1T_PITCH + lane], __shfl_sync(0xffffffffu, hv, k + 0), p0);
        p1 = fmaf(w1t[(k + 1) * W1T_PITCH + lane], __shfl_sync(0xffffffffu, hv, k + 1), p1);
        p2 = fmaf(w1t[(k + 2) * W1T_PITCH + lane], __shfl_sync(0xffffffffu, hv, k + 2), p2);
        p3 = fmaf(w1t[(k + 3) * W1T_PITCH + lane], __shfl_sync(0xffffffffu, hv, k + 3), p3);
    }
    float x1 = b1s[lane] + ((p0 + p1) + (p2 + p3));
    x1 = x1 >= 0.f ? x1 : 0.01f * x1;

    float q0 = 0.f, q1 = 0.f, q2 = 0.f, q3 = 0.f;
#pragma unroll
    for (int k = 0; k < NH; k += 4) {
        q0 = fmaf(w2t[(k + 0) * W1T_PITCH + lane], __shfl_sync(0xffffffffu, x1, k + 0), q0);
        q1 = fmaf(w2t[(k + 1) * W1T_PITCH + lane], __shfl_sync(0xffffffffu, x1, k + 1), q1);
        q2 = fmaf(w2t[(k + 2) * W1T_PITCH + lane], __shfl_sync(0xffffffffu, x1, k + 2), q2);
        q3 = fmaf(w2t[(k + 3) * W1T_PITCH + lane], __shfl_sync(0xffffffffu, x1, k + 3), q3);
    }
#pragma unroll
    for (int k = 0; k < NH; k += 4) {
        q0 = fmaf(w2t[(NH + k + 0) * W1T_PITCH + lane], __shfl_sync(0xffffffffu, hv, k + 0), q0);
        q1 = fmaf(w2t[(NH + k + 1) * W1T_PITCH + lane], __shfl_sync(0xffffffffu, hv, k + 1), q1);
        q2 = fmaf(w2t[(NH + k + 2) * W1T_PITCH + lane], __shfl_sync(0xffffffffu, hv, k + 2), q2);
        q3 = fmaf(w2t[(NH + k + 3) * W1T_PITCH + lane], __shfl_sync(0xffffffffu, hv, k + 3), q3);
    }
    float x2 = b2s[lane] + ((q0 + q1) + (q2 + q3));
    x2 = x2 >= 0.f ? x2 : 0.01f * x2;

    float v = Wd[(size_t)n * 2 * NH + lane] * x2
            + Wd[(size_t)n * 2 * NH + NH + lane] * hv;
#pragma unroll
    for (int o = 16; o; o >>= 1) v += __shfl_xor_sync(0xffffffffu, v, o);
    if (lane == 0) out[(size_t)b * NN + n] = v + bd[n];
}

extern "C" void kernel_launch(void* const* d_in, const int* in_sizes, int n_in,
                              void* d_out, int out_size)
{
    (void)in_sizes; (void)n_in; (void)out_size;
    const float* x  = (const float*)d_in[0];
    const float* g  = (const float*)d_in[2];
    const float* Wu = (const float*)d_in[5];
    const float* bu = (const float*)d_in[6];
    const float* Wc = (const float*)d_in[7];
    const float* bc = (const float*)d_in[8];
    const float* h0 = (const float*)d_in[9];
    const float* W1 = (const float*)d_in[10];
    const float* b1 = (const float*)d_in[11];
    const float* W2 = (const float*)d_in[12];
    const float* b2 = (const float*)d_in[13];
    const float* Wd = (const float*)d_in[14];
    const float* bd = (const float*)d_in[15];
    float* out = (float*)d_out;

    xh_kernel<<<NB * 16, 256>>>(x);
    prep_kernel<<<16384, 256>>>(g, Wu, Wc);

    cudaFuncSetAttribute(gemm_gru_kernel,
                         cudaFuncAttributeMaxDynamicSharedMemorySize, SMEM_BYTES);
    dim3 grid(8, 16, NB);
    gemm_gru_kernel<<<grid, 256, SMEM_BYTES>>>(bu, bc, h0);

    head_kernel<<<(NB * NN) / 32, 1024>>>(W1, b1, W2, b2, Wd, bd, out);
}

// round 16
// speedup vs baseline: 1.2751x; 1.1371x over previous
#include <cuda_runtime.h>
#include <cuda_fp16.h>
#include <cstdint>

// Problem constants
#define NN 1024   // nodes
#define NB 8      // batch
#define NS 64     // timesteps
#define NH 32     // hidden

// GEMM tiling: per CTA, M=128 (n rows) x N=256 cols (2u x 64t x 2 gates), K=1024
#define BK 64
#define NKT 16           // k-iters
#define STAGES 3
#define AP 80            // halfs per A row (64 data + 16 pad) -> conflict-free LDS.64
#define BP 80            // halfs per B col
#define ACHUNK (128 * AP)   // 10240 halfs per (tile, kchunk)
#define BCHUNK (256 * BP)   // 20480
#define ABYTES (ACHUNK * 2) // 20480 B
#define BBYTES (BCHUNK * 2) // 40960 B
#define SBYTES (ABYTES + BBYTES)        // 61440 per stage
#define ZPITCH 257
#define SMEM_BYTES (STAGES * SBYTES)    // 184320; Z tile (131584) aliases this

// Precomputed operand buffers (16B-aligned; padded rows, global layout == smem layout)
__device__ __align__(16) __half g_A[(size_t)NB * 8 * NKT * ACHUNK];    // ~21 MB
__device__ __align__(16) __half g_B[(size_t)NB * 16 * NKT * BCHUNK];   // ~84 MB
__device__ __align__(16) __half2 g_xh[(size_t)NB * NS * (NN / 2)];     // xh[b][t][m/2]
__device__ __align__(16) float  g_h[NB * NN * NH];

// ---------------- helpers ----------------
__device__ __forceinline__ uint32_t smem_u32(const void* p) {
    uint32_t a;
    asm("{ .reg .u64 t; cvta.to.shared.u64 t, %1; cvt.u32.u64 %0, t; }" : "=r"(a) : "l"(p));
    return a;
}
__device__ __forceinline__ void cp16(uint32_t s, const void* g) {
    asm volatile("cp.async.cg.shared.global [%0], [%1], 16;" :: "r"(s), "l"(g) : "memory");
}
__device__ __forceinline__ void cp_commit() {
    asm volatile("cp.async.commit_group;" ::: "memory");
}
template <int N>
__device__ __forceinline__ void cp_wait() {
    asm volatile("cp.async.wait_group %0;" :: "n"(N) : "memory");
}
__device__ __forceinline__ void mma_f16(float c[4], uint2 alo, uint2 ahi, uint2 bf) {
    asm volatile(
        "mma.sync.aligned.m16n8k16.row.col.f32.f16.f16.f32 "
        "{%0,%1,%2,%3}, {%4,%5,%6,%7}, {%8,%9}, {%0,%1,%2,%3};\n"
        : "+f"(c[0]), "+f"(c[1]), "+f"(c[2]), "+f"(c[3])
        : "r"(alo.x), "r"(ahi.x), "r"(alo.y), "r"(ahi.y), "r"(bf.x), "r"(bf.y));
}
__device__ __forceinline__ uint32_t pack2(float a, float b) {
    __half2 h = __halves2half2(__float2half_rn(a), __float2half_rn(b));
    return *reinterpret_cast<uint32_t*>(&h);
}
__device__ __forceinline__ float tanh_fast(float x) {
    float r;
    asm("tanh.approx.f32 %0, %1;" : "=f"(r) : "f"(x));
    return r;
}

// ---------------- prep: xh[b][t][m/2] via coalesced smem transpose ----------------
#define XTP 68   // 272B rows keep float4 16B-aligned
__global__ void __launch_bounds__(256)
xh_kernel(const float* __restrict__ X) {
    __shared__ float s[64 * XTP];
    const int tid  = threadIdx.x;
    const int mblk = blockIdx.x & 15;
    const int b    = blockIdx.x >> 4;

    const float* src = X + (size_t)b * NN * NS + (size_t)(mblk * 64) * NS;
#pragma unroll
    for (int i = 0; i < 4; i++) {
        int slot = tid + i * 256;
        int row = slot >> 4, j = slot & 15;
        *(float4*)(s + row * XTP + j * 4) = *(const float4*)(src + (size_t)row * NS + j * 4);
    }
    __syncthreads();

    const int t = tid >> 2;
    const int g = tid & 3;
    uint32_t r[8];
#pragma unroll
    for (int i = 0; i < 8; i++) {
        int ml = 8 * g + i;
        r[i] = pack2(s[(2 * ml) * XTP + t], s[(2 * ml + 1) * XTP + t]);
    }
    uint32_t* dst = (uint32_t*)(g_xh + (size_t)(b * NS + t) * 512 + mblk * 32 + 8 * g);
    *(uint4*)(dst)     = make_uint4(r[0], r[1], r[2], r[3]);
    *(uint4*)(dst + 4) = make_uint4(r[4], r[5], r[6], r[7]);
}

// ---------------- fused prep: blocks [0,8192) = B-convert, [8192,16384) = A-convert ----
__global__ void __launch_bounds__(256)
prep_kernel(const float* __restrict__ G,
            const float* __restrict__ Wu, const float* __restrict__ Wc) {
    const int tid = threadIdx.x;
    if (blockIdx.x < 8192) {
        // ---- B: B[col,k] = h(w[k]) * h(x[k,t]), fragment-permuted ----
        int idx = blockIdx.x * 256 + tid;   // 2,097,152
        int ks  = idx & 3;
        int col = (idx >> 2) & 255;
        int kt  = (idx >> 10) & 15;
        int nt  = (idx >> 14) & 15;
        int b   = idx >> 18;
        int ul = col >> 7, t = (col & 127) >> 1, gate = col & 1;
        int u  = nt * 2 + ul;

        const __half2* xp = g_xh + (size_t)(b * NS + t) * 512 + kt * 32 + ks * 8;
        const float*   wf = (gate ? Wc : Wu) + (size_t)u * NN + kt * 64 + ks * 16;

        float4 f0 = *(const float4*)(wf + 0);
        float4 f1 = *(const float4*)(wf + 4);
        float4 f2 = *(const float4*)(wf + 8);
        float4 f3 = *(const float4*)(wf + 12);
        uint32_t w[8];
        w[0] = pack2(f0.x, f0.y); w[1] = pack2(f0.z, f0.w);
        w[2] = pack2(f1.x, f1.y); w[3] = pack2(f1.z, f1.w);
        w[4] = pack2(f2.x, f2.y); w[5] = pack2(f2.z, f2.w);
        w[6] = pack2(f3.x, f3.y); w[7] = pack2(f3.z, f3.w);

        uint32_t r[8];
#pragma unroll
        for (int j = 0; j < 8; j++) {
            __half2 wv = *reinterpret_cast<__half2*>(&w[j]);
            __half2 v  = __hmul2(wv, xp[j]);
            r[j] = *reinterpret_cast<uint32_t*>(&v);
        }
        uint4 o0 = make_uint4(r[0], r[4], r[1], r[5]);
        uint4 o1 = make_uint4(r[2], r[6], r[3], r[7]);
        uint4* dst = reinterpret_cast<uint4*>(
            g_B + (size_t)((b * 16 + nt) * 16 + kt) * BCHUNK + col * BP + ks * 16);
        dst[0] = o0;
        dst[1] = o1;
    } else {
        // ---- A: half(G), fragment-permuted ----
        int idx = (blockIdx.x - 8192) * 256 + tid;   // 2,097,152 quads
        int q   = idx & 3;
        int ks  = (idx >> 2) & 3;
        int row = (idx >> 4) & 127;
        int kt  = (idx >> 11) & 15;
        int mt  = (idx >> 15) & 7;
        int b   = idx >> 18;
        const float* src = G + ((size_t)b * NN + mt * 128 + row) * NN + kt * 64 + ks * 16 + 2 * q;
        uint2 v;
        v.x = pack2(src[0], src[1]);
        v.y = pack2(src[8], src[9]);
        *reinterpret_cast<uint2*>(
            g_A + (size_t)((b * 8 + mt) * 16 + kt) * ACHUNK + row * AP + ks * 16 + q * 4) = v;
    }
}

// ---------------- main: fp16 HMMA GEMM (3-stage cp.async ring) + fused GRU ----------------
__global__ void __launch_bounds__(256, 1)
gemm_gru_kernel(const float* __restrict__ bu, const float* __restrict__ bc,
                const float* __restrict__ h0)
{
    extern __shared__ __align__(16) char smem[];
    const uint32_t sb = smem_u32(smem);

    const int tid  = threadIdx.x;
    const int wid  = tid >> 5;
    const int lane = tid & 31;
    const int wm   = wid >> 2;
    const int wn   = wid & 3;
    const int grp  = lane >> 2;
    const int qid  = lane & 3;

    const int mt = blockIdx.x;
    const int nt = blockIdx.y;
    const int b  = blockIdx.z;

    const __half* Asrc = g_A + (size_t)((b * 8 + mt) * 16) * ACHUNK;
    const __half* Bsrc = g_B + (size_t)((b * 16 + nt) * 16) * BCHUNK;

    float acc[4][8][4];
#pragma unroll
    for (int i = 0; i < 4; i++)
#pragma unroll
        for (int j = 0; j < 8; j++)
#pragma unroll
            for (int r = 0; r < 4; r++) acc[i][j][r] = 0.f;

// Global layout == smem layout: fully linear cp.async (proven fastest)
#define ISSUE(KT, SLOT) do {                                                       \
    uint32_t sa = sb + (SLOT) * SBYTES;                                            \
    const char* ga = (const char*)(Asrc + (size_t)(KT) * ACHUNK);                  \
    _Pragma("unroll")                                                              \
    for (int i = 0; i < 5; i++)                                                    \
        cp16(sa + tid * 16 + i * 4096, ga + tid * 16 + i * 4096);                  \
    uint32_t sB = sa + ABYTES;                                                     \
    const char* gb = (const char*)(Bsrc + (size_t)(KT) * BCHUNK);                  \
    _Pragma("unroll")                                                              \
    for (int i = 0; i < 10; i++)                                                   \
        cp16(sB + tid * 16 + i * 4096, gb + tid * 16 + i * 4096);                  \
    cp_commit();                                                                   \
} while (0)

#define COMPUTE(SLOT) do {                                                         \
    const __half* Ab = (const __half*)(smem + (SLOT) * SBYTES);                    \
    const __half* Bb = (const __half*)(smem + (SLOT) * SBYTES + ABYTES);           \
    _Pragma("unroll")                                                              \
    for (int ks = 0; ks < 4; ks++) {                                               \
        uint2 alo[4], ahi[4], bf[8];                                               \
        _Pragma("unroll")                                                          \
        for (int mi = 0; mi < 4; mi++) {                                           \
            const __half* ap = Ab + (wm * 64 + mi * 16 + grp) * AP + ks * 16 + qid * 4; \
            alo[mi] = *reinterpret_cast<const uint2*>(ap);                         \
            ahi[mi] = *reinterpret_cast<const uint2*>(ap + 8 * AP);                \
        }                                                                          \
        _Pragma("unroll")                                                          \
        for (int nj = 0; nj < 8; nj++)                                             \
            bf[nj] = *reinterpret_cast<const uint2*>(                              \
                Bb + (wn * 64 + nj * 8 + grp) * BP + ks * 16 + qid * 4);           \
        _Pragma("unroll")                                                          \
        for (int mi = 0; mi < 4; mi++)                                             \
        _Pragma("unroll")                                                          \
        for (int nj = 0; nj < 8; nj++)                                             \
            mma_f16(acc[mi][nj], alo[mi], ahi[mi], bf[nj]);                        \
    }                                                                              \
} while (0)

    // Prologue: stages 0 and 1 in flight
    ISSUE(0, 0);
    ISSUE(1, 1);

    int slot = 0;
#pragma unroll 1
    for (int kt = 0; kt < NKT; kt++) {
        if (kt < NKT - 1) cp_wait<1>();
        else              cp_wait<0>();
        __syncthreads();
        if (kt + 2 < NKT) {
            int ns = slot + 2; if (ns >= STAGES) ns -= STAGES;
            ISSUE(kt + 2, ns);
        }
        COMPUTE(slot);
        if (++slot == STAGES) slot = 0;
    }
    __syncthreads();   // all COMPUTE done before Z aliases staging smem

    // ---- Epilogue: dump Z to smem, run the GRU recurrence over t ----
    float* Zs = (float*)smem;   // [128][ZPITCH]
#pragma unroll
    for (int mi = 0; mi < 4; mi++)
#pragma unroll
        for (int nj = 0; nj < 8; nj++)
#pragma unroll
            for (int r = 0; r < 4; r++) {
                int row = wm * 64 + mi * 16 + grp + ((r >> 1) ? 8 : 0);
                int col = wn * 64 + nj * 8 + qid * 2 + (r & 1);
                Zs[row * ZPITCH + col] = acc[mi][nj][r];
            }
    __syncthreads();

    {
        const int row = tid & 127;
        const int ul  = tid >> 7;
        const int n   = mt * 128 + row;
        const int u   = nt * 2 + ul;
        float h = h0[(size_t)u * NN + n];
        const float buv = bu[u];
        const float bcv = bc[u];
        const float* zrow = Zs + row * ZPITCH + ul * 128;
#pragma unroll 1
        for (int t = 0; t < NS; t++) {
            float zu = zrow[2 * t]     + buv;
            float zc = zrow[2 * t + 1] + bcv;
            // sigmoid(x) = 0.5*tanh(0.5x)+0.5 ; both activations on the MUFU tanh path
            float ug = fmaf(0.5f, tanh_fast(0.5f * zu), 0.5f);
            float cg = tanh_fast(zc);
            h = fmaf(ug, h - cg, cg);
        }
        g_h[((size_t)b * NN + n) * NH + u] = h;
    }
#undef ISSUE
#undef COMPUTE
}

// ---------------- prediction head (1024-thread blocks) ----------------
#define W1T_PITCH 33
__global__ void __launch_bounds__(1024)
head_kernel(const float* __restrict__ W1, const float* __restrict__ b1,
            const float* __restrict__ W2, const float* __restrict__ b2,
            const float* __restrict__ Wd, const float* __restrict__ bd,
            float* __restrict__ out)
{
    __shared__ float w1t[NH * W1T_PITCH];
    __shared__ float w2t[2 * NH * W1T_PITCH];
    __shared__ float b1s[NH], b2s[NH];

    const int tid = threadIdx.x;
    for (int i = tid; i < NH * NH; i += 1024) {
        int u = i >> 5, k = i & 31;
        w1t[k * W1T_PITCH + u] = W1[i];
    }
    for (int i = tid; i < NH * 2 * NH; i += 1024) {
        int u = i >> 6, k = i & 63;
        w2t[k * W1T_PITCH + u] = W2[i];
    }
    if (tid < NH) { b1s[tid] = b1[tid]; b2s[tid] = b2[tid]; }
    __syncthreads();

    const int warp = blockIdx.x * 32 + (tid >> 5);
    const int lane = tid & 31;
    const int b = warp >> 10;
    const int n = warp & (NN - 1);

    const float hv = g_h[((size_t)b * NN + n) * NH + lane];

    float p0 = 0.f, p1 = 0.f, p2 = 0.f, p3 = 0.f;
#pragma unroll
    for (int k = 0; k < NH; k += 4) {
        p0 = fmaf(w1t[(k + 0) * W1T_PITCH + lane], __shfl_sync(0xffffffffu, hv, k + 0), p0);
        p1 = fmaf(w1t[(k + 1) * W1T_PITCH + lane], __shfl_sync(0xffffffffu, hv, k + 1), p1);
        p2 = fmaf(w1t[(k + 2) * W1T_PITCH + lane], __shfl_sync(0xffffffffu, hv, k + 2), p2);
        p3 = fmaf(w1t[(k + 3) * W1T_PITCH + lane], __shfl_sync(0xffffffffu, hv, k + 3), p3);
    }
    float x1 = b1s[lane] + ((p0 + p1) + (p2 + p3));
    x1 = x1 >= 0.f ? x1 : 0.01f * x1;

    float q0 = 0.f, q1 = 0.f, q2 = 0.f, q3 = 0.f;
#pragma unroll
    for (int k = 0; k < NH; k += 4) {
        q0 = fmaf(w2t[(k + 0) * W1T_PITCH + lane], __shfl_sync(0xffffffffu, x1, k + 0), q0);
        q1 = fmaf(w2t[(k + 1) * W1T_PITCH + lane], __shfl_sync(0xffffffffu, x1, k + 1), q1);
        q2 = fmaf(w2t[(k + 2) * W1T_PITCH + lane], __shfl_sync(0xffffffffu, x1, k + 2), q2);
        q3 = fmaf(w2t[(k + 3) * W1T_PITCH + lane], __shfl_sync(0xffffffffu, x1, k + 3), q3);
    }
#pragma unroll
    for (int k = 0; k < NH; k += 4) {
        q0 = fmaf(w2t[(NH + k + 0) * W1T_PITCH + lane], __shfl_sync(0xffffffffu, hv, k + 0), q0);
        q1 = fmaf(w2t[(NH + k + 1) * W1T_PITCH + lane], __shfl_sync(0xffffffffu, hv, k + 1), q1);
        q2 = fmaf(w2t[(NH + k + 2) * W1T_PITCH + lane], __shfl_sync(0xffffffffu, hv, k + 2), q2);
        q3 = fmaf(w2t[(NH + k + 3) * W1T_PITCH + lane], __shfl_sync(0xffffffffu, hv, k + 3), q3);
    }
    float x2 = b2s[lane] + ((q0 + q1) + (q2 + q3));
    x2 = x2 >= 0.f ? x2 : 0.01f * x2;

    float v = Wd[(size_t)n * 2 * NH + lane] * x2
            + Wd[(size_t)n * 2 * NH + NH + lane] * hv;
#pragma unroll
    for (int o = 16; o; o >>= 1) v += __shfl_xor_sync(0xffffffffu, v, o);
    if (lane == 0) out[(size_t)b * NN + n] = v + bd[n];
}

extern "C" void kernel_launch(void* const* d_in, const int* in_sizes, int n_in,
                              void* d_out, int out_size)
{
    (void)in_sizes; (void)n_in; (void)out_size;
    const float* x  = (const float*)d_in[0];
    const float* g  = (const float*)d_in[2];
    const float* Wu = (const float*)d_in[5];
    const float* bu = (const float*)d_in[6];
    const float* Wc = (const float*)d_in[7];
    const float* bc = (const float*)d_in[8];
    const float* h0 = (const float*)d_in[9];
    const float* W1 = (const float*)d_in[10];
    const float* b1 = (const float*)d_in[11];
    const float* W2 = (const float*)d_in[12];
    const float* b2 = (const float*)d_in[13];
    const float* Wd = (const float*)d_in[14];
    const float* bd = (const float*)d_in[15];
    float* out = (float*)d_out;

    xh_kernel<<<NB * 16, 256>>>(x);
    prep_kernel<<<16384, 256>>>(g, Wu, Wc);

    cudaFuncSetAttribute(gemm_gru_kernel,
                         cudaFuncAttributeMaxDynamicSharedMemorySize, SMEM_BYTES);
    dim3 grid(8, 16, NB);
    gemm_gru_kernel<<<grid, 256, SMEM_BYTES>>>(bu, bc, h0);

    head_kernel<<<(NB * NN) / 32, 1024>>>(W1, b1, W2, b2, Wd, bd, out);
}

// round 17
// speedup vs baseline: 1.3136x; 1.0302x over previous
#include <cuda_runtime.h>
#include <cuda_fp16.h>
#include <cstdint>

// Problem constants
#define NN 1024   // nodes
#define NB 8      // batch
#define NS 64     // timesteps
#define NH 32     // hidden

// GEMM tiling: per CTA, M=128 (n rows) x N=256 cols (2u x 64t x 2 gates), K=1024
#define BK 64
#define NKT 16           // k-iters
#define STAGES 3
#define AP 80            // halfs per A row (64 data + 16 pad) -> conflict-free LDS.64
#define BP 80            // halfs per B col
#define ACHUNK (128 * AP)   // 10240 halfs per (tile, kchunk)
#define BCHUNK (256 * BP)   // 20480
#define ABYTES (ACHUNK * 2) // 20480 B
#define BBYTES (BCHUNK * 2) // 40960 B
#define SBYTES (ABYTES + BBYTES)        // 61440 per stage
#define ZPITCH 257
#define SMEM_BYTES (STAGES * SBYTES)    // 184320; Z tile (131584) aliases this

// Precomputed operand buffers (16B-aligned; padded rows, global layout == smem layout)
__device__ __align__(16) __half g_A[(size_t)NB * 8 * NKT * ACHUNK];    // ~21 MB
__device__ __align__(16) __half g_B[(size_t)NB * 16 * NKT * BCHUNK];   // ~84 MB
__device__ __align__(16) __half2 g_xh[(size_t)NB * NS * (NN / 2)];     // xh[b][t][m/2]
__device__ __align__(16) float  g_h[NB * NN * NH];

// ---------------- helpers ----------------
__device__ __forceinline__ uint32_t smem_u32(const void* p) {
    uint32_t a;
    asm("{ .reg .u64 t; cvta.to.shared.u64 t, %1; cvt.u32.u64 %0, t; }" : "=r"(a) : "l"(p));
    return a;
}
__device__ __forceinline__ void cp16(uint32_t s, const void* g) {
    asm volatile("cp.async.cg.shared.global [%0], [%1], 16;" :: "r"(s), "l"(g) : "memory");
}
__device__ __forceinline__ void cp_commit() {
    asm volatile("cp.async.commit_group;" ::: "memory");
}
template <int N>
__device__ __forceinline__ void cp_wait() {
    asm volatile("cp.async.wait_group %0;" :: "n"(N) : "memory");
}
__device__ __forceinline__ void mma_f16(float c[4], uint2 alo, uint2 ahi, uint2 bf) {
    asm volatile(
        "mma.sync.aligned.m16n8k16.row.col.f32.f16.f16.f32 "
        "{%0,%1,%2,%3}, {%4,%5,%6,%7}, {%8,%9}, {%0,%1,%2,%3};\n"
        : "+f"(c[0]), "+f"(c[1]), "+f"(c[2]), "+f"(c[3])
        : "r"(alo.x), "r"(ahi.x), "r"(alo.y), "r"(ahi.y), "r"(bf.x), "r"(bf.y));
}
__device__ __forceinline__ uint32_t pack2(float a, float b) {
    __half2 h = __halves2half2(__float2half_rn(a), __float2half_rn(b));
    return *reinterpret_cast<uint32_t*>(&h);
}
__device__ __forceinline__ float tanh_fast(float x) {
    float r;
    asm("tanh.approx.f32 %0, %1;" : "=f"(r) : "f"(x));
    return r;
}

// ---------------- prep: xh[b][t][m/2] via coalesced smem transpose ----------------
#define XTP 68   // 272B rows keep float4 16B-aligned
__global__ void __launch_bounds__(256)
xh_kernel(const float* __restrict__ X) {
    __shared__ float s[64 * XTP];
    const int tid  = threadIdx.x;
    const int mblk = blockIdx.x & 15;
    const int b    = blockIdx.x >> 4;

    const float* src = X + (size_t)b * NN * NS + (size_t)(mblk * 64) * NS;
#pragma unroll
    for (int i = 0; i < 4; i++) {
        int slot = tid + i * 256;
        int row = slot >> 4, j = slot & 15;
        *(float4*)(s + row * XTP + j * 4) = *(const float4*)(src + (size_t)row * NS + j * 4);
    }
    __syncthreads();

    const int t = tid >> 2;
    const int g = tid & 3;
    uint32_t r[8];
#pragma unroll
    for (int i = 0; i < 8; i++) {
        int ml = 8 * g + i;
        r[i] = pack2(s[(2 * ml) * XTP + t], s[(2 * ml + 1) * XTP + t]);
    }
    uint32_t* dst = (uint32_t*)(g_xh + (size_t)(b * NS + t) * 512 + mblk * 32 + 8 * g);
    *(uint4*)(dst)     = make_uint4(r[0], r[1], r[2], r[3]);
    *(uint4*)(dst + 4) = make_uint4(r[4], r[5], r[6], r[7]);
}

// ---------------- fused prep: blocks [0,8192) = B-convert, [8192,16384) = A-convert ----
__global__ void __launch_bounds__(256)
prep_kernel(const float* __restrict__ G,
            const float* __restrict__ Wu, const float* __restrict__ Wc) {
    const int tid = threadIdx.x;
    if (blockIdx.x < 8192) {
        // ---- B: B[col,k] = h(w[k]) * h(x[k,t]), fragment-permuted ----
        int idx = blockIdx.x * 256 + tid;   // 2,097,152
        int ks  = idx & 3;
        int col = (idx >> 2) & 255;
        int kt  = (idx >> 10) & 15;
        int nt  = (idx >> 14) & 15;
        int b   = idx >> 18;
        int ul = col >> 7, t = (col & 127) >> 1, gate = col & 1;
        int u  = nt * 2 + ul;

        const __half2* xp = g_xh + (size_t)(b * NS + t) * 512 + kt * 32 + ks * 8;
        const float*   wf = (gate ? Wc : Wu) + (size_t)u * NN + kt * 64 + ks * 16;

        float4 f0 = *(const float4*)(wf + 0);
        float4 f1 = *(const float4*)(wf + 4);
        float4 f2 = *(const float4*)(wf + 8);
        float4 f3 = *(const float4*)(wf + 12);
        uint32_t w[8];
        w[0] = pack2(f0.x, f0.y); w[1] = pack2(f0.z, f0.w);
        w[2] = pack2(f1.x, f1.y); w[3] = pack2(f1.z, f1.w);
        w[4] = pack2(f2.x, f2.y); w[5] = pack2(f2.z, f2.w);
        w[6] = pack2(f3.x, f3.y); w[7] = pack2(f3.z, f3.w);

        uint32_t r[8];
#pragma unroll
        for (int j = 0; j < 8; j++) {
            __half2 wv = *reinterpret_cast<__half2*>(&w[j]);
            __half2 v  = __hmul2(wv, xp[j]);
            r[j] = *reinterpret_cast<uint32_t*>(&v);
        }
        uint4 o0 = make_uint4(r[0], r[4], r[1], r[5]);
        uint4 o1 = make_uint4(r[2], r[6], r[3], r[7]);
        uint4* dst = reinterpret_cast<uint4*>(
            g_B + (size_t)((b * 16 + nt) * 16 + kt) * BCHUNK + col * BP + ks * 16);
        dst[0] = o0;
        dst[1] = o1;
    } else {
        // ---- A: half(G), fragment-permuted ----
        int idx = (blockIdx.x - 8192) * 256 + tid;   // 2,097,152 quads
        int q   = idx & 3;
        int ks  = (idx >> 2) & 3;
        int row = (idx >> 4) & 127;
        int kt  = (idx >> 11) & 15;
        int mt  = (idx >> 15) & 7;
        int b   = idx >> 18;
        const float* src = G + ((size_t)b * NN + mt * 128 + row) * NN + kt * 64 + ks * 16 + 2 * q;
        uint2 v;
        v.x = pack2(src[0], src[1]);
        v.y = pack2(src[8], src[9]);
        *reinterpret_cast<uint2*>(
            g_A + (size_t)((b * 8 + mt) * 16 + kt) * ACHUNK + row * AP + ks * 16 + q * 4) = v;
    }
}

// ---------------- main: fp16 HMMA GEMM (3-stage cp.async ring) + fused GRU ----------------
__global__ void __launch_bounds__(256, 1)
gemm_gru_kernel(const float* __restrict__ bu, const float* __restrict__ bc,
                const float* __restrict__ h0)
{
    extern __shared__ __align__(16) char smem[];
    const uint32_t sb = smem_u32(smem);

    const int tid  = threadIdx.x;
    const int wid  = tid >> 5;
    const int lane = tid & 31;
    const int wm   = wid >> 2;
    const int wn   = wid & 3;
    const int grp  = lane >> 2;
    const int qid  = lane & 3;

    const int mt = blockIdx.x;
    const int nt = blockIdx.y;
    const int b  = blockIdx.z;

    const __half* Asrc = g_A + (size_t)((b * 8 + mt) * 16) * ACHUNK;
    const __half* Bsrc = g_B + (size_t)((b * 16 + nt) * 16) * BCHUNK;

    float acc[4][8][4];
#pragma unroll
    for (int i = 0; i < 4; i++)
#pragma unroll
        for (int j = 0; j < 8; j++)
#pragma unroll
            for (int r = 0; r < 4; r++) acc[i][j][r] = 0.f;

// Global layout == smem layout: fully linear cp.async (proven fastest)
#define ISSUE(KT, SLOT) do {                                                       \
    uint32_t sa = sb + (SLOT) * SBYTES;                                            \
    const char* ga = (const char*)(Asrc + (size_t)(KT) * ACHUNK);                  \
    _Pragma("unroll")                                                              \
    for (int i = 0; i < 5; i++)                                                    \
        cp16(sa + tid * 16 + i * 4096, ga + tid * 16 + i * 4096);                  \
    uint32_t sB = sa + ABYTES;                                                     \
    const char* gb = (const char*)(Bsrc + (size_t)(KT) * BCHUNK);                  \
    _Pragma("unroll")                                                              \
    for (int i = 0; i < 10; i++)                                                   \
        cp16(sB + tid * 16 + i * 4096, gb + tid * 16 + i * 4096);                  \
    cp_commit();                                                                   \
} while (0)

#define COMPUTE(SLOT) do {                                                         \
    const __half* Ab = (const __half*)(smem + (SLOT) * SBYTES);                    \
    const __half* Bb = (const __half*)(smem + (SLOT) * SBYTES + ABYTES);           \
    _Pragma("unroll")                                                              \
    for (int ks = 0; ks < 4; ks++) {                                               \
        uint2 alo[4], ahi[4], bf[8];                                               \
        _Pragma("unroll")                                                          \
        for (int mi = 0; mi < 4; mi++) {                                           \
            const __half* ap = Ab + (wm * 64 + mi * 16 + grp) * AP + ks * 16 + qid * 4; \
            alo[mi] = *reinterpret_cast<const uint2*>(ap);                         \
            ahi[mi] = *reinterpret_cast<const uint2*>(ap + 8 * AP);                \
        }                                                                          \
        _Pragma("unroll")                                                          \
        for (int nj = 0; nj < 8; nj++)                                             \
            bf[nj] = *reinterpret_cast<const uint2*>(                              \
                Bb + (wn * 64 + nj * 8 + grp) * BP + ks * 16 + qid * 4);           \
        _Pragma("unroll")                                                          \
        for (int mi = 0; mi < 4; mi++)                                             \
        _Pragma("unroll")                                                          \
        for (int nj = 0; nj < 8; nj++)                                             \
            mma_f16(acc[mi][nj], alo[mi], ahi[mi], bf[nj]);                        \
    }                                                                              \
} while (0)

    // Prologue: stages 0 and 1 in flight
    ISSUE(0, 0);
    ISSUE(1, 1);

    int slot = 0;
#pragma unroll 1
    for (int kt = 0; kt < NKT; kt++) {
        if (kt < NKT - 1) cp_wait<1>();
        else              cp_wait<0>();
        __syncthreads();
        if (kt + 2 < NKT) {
            int ns = slot + 2; if (ns >= STAGES) ns -= STAGES;
            ISSUE(kt + 2, ns);
        }
        COMPUTE(slot);
        if (++slot == STAGES) slot = 0;
    }
    __syncthreads();   // all COMPUTE done before Z aliases staging smem

    // ---- Epilogue: dump Z to smem, run the GRU recurrence over t ----
    float* Zs = (float*)smem;   // [128][ZPITCH]
#pragma unroll
    for (int mi = 0; mi < 4; mi++)
#pragma unroll
        for (int nj = 0; nj < 8; nj++)
#pragma unroll
            for (int r = 0; r < 4; r++) {
                int row = wm * 64 + mi * 16 + grp + ((r >> 1) ? 8 : 0);
                int col = wn * 64 + nj * 8 + qid * 2 + (r & 1);
                Zs[row * ZPITCH + col] = acc[mi][nj][r];
            }
    __syncthreads();

    {
        const int row = tid & 127;
        const int ul  = tid >> 7;
        const int n   = mt * 128 + row;
        const int u   = nt * 2 + ul;
        float h = h0[(size_t)u * NN + n];
        const float buv = bu[u];
        const float bcv = bc[u];
        const float* zrow = Zs + row * ZPITCH + ul * 128;
        // 16-step blocks: batch the 32 MUFUs (throughput-bound), then run the
        // pure-FMA recurrence chain (latency-bound but short).
#pragma unroll
        for (int t0 = 0; t0 < NS; t0 += 16) {
            float ug[16], cg[16];
#pragma unroll
            for (int i = 0; i < 16; i++) {
                float zu = zrow[2 * (t0 + i)]     + buv;
                float zc = zrow[2 * (t0 + i) + 1] + bcv;
                ug[i] = fmaf(0.5f, tanh_fast(0.5f * zu), 0.5f);
                cg[i] = tanh_fast(zc);
            }
#pragma unroll
            for (int i = 0; i < 16; i++)
                h = fmaf(ug[i], h - cg[i], cg[i]);
        }
        g_h[((size_t)b * NN + n) * NH + u] = h;
    }
#undef ISSUE
#undef COMPUTE
}

// ---------------- prediction head (1024-thread blocks) ----------------
#define W1T_PITCH 33
__global__ void __launch_bounds__(1024)
head_kernel(const float* __restrict__ W1, const float* __restrict__ b1,
            const float* __restrict__ W2, const float* __restrict__ b2,
            const float* __restrict__ Wd, const float* __restrict__ bd,
            float* __restrict__ out)
{
    __shared__ float w1t[NH * W1T_PITCH];
    __shared__ float w2t[2 * NH * W1T_PITCH];
    __shared__ float b1s[NH], b2s[NH];

    const int tid = threadIdx.x;
    for (int i = tid; i < NH * NH; i += 1024) {
        int u = i >> 5, k = i & 31;
        w1t[k * W1T_PITCH + u] = W1[i];
    }
    for (int i = tid; i < NH * 2 * NH; i += 1024) {
        int u = i >> 6, k = i & 63;
        w2t[k * W1T_PITCH + u] = W2[i];
    }
    if (tid < NH) { b1s[tid] = b1[tid]; b2s[tid] = b2[tid]; }
    __syncthreads();

    const int warp = blockIdx.x * 32 + (tid >> 5);
    const int lane = tid & 31;
    const int b = warp >> 10;
    const int n = warp & (NN - 1);

    const float hv = g_h[((size_t)b * NN + n) * NH + lane];

    float p0 = 0.f, p1 = 0.f, p2 = 0.f, p3 = 0.f;
#pragma unroll
    for (int k = 0; k < NH; k += 4) {
        p0 = fmaf(w1t[(k + 0) * W1T_PITCH + lane], __shfl_sync(0xffffffffu, hv, k + 0), p0);
        p1 = fmaf(w1t[(k + 1) * W1T_PITCH + lane], __shfl_sync(0xffffffffu, hv, k + 1), p1);
        p2 = fmaf(w1t[(k + 2) * W1T_PITCH + lane], __shfl_sync(0xffffffffu, hv, k + 2), p2);
        p3 = fmaf(w1t[(k + 3) * W1T_PITCH + lane], __shfl_sync(0xffffffffu, hv, k + 3), p3);
    }
    float x1 = b1s[lane] + ((p0 + p1) + (p2 + p3));
    x1 = x1 >= 0.f ? x1 : 0.01f * x1;

    float q0 = 0.f, q1 = 0.f, q2 = 0.f, q3 = 0.f;
#pragma unroll
    for (int k = 0; k < NH; k += 4) {
        q0 = fmaf(w2t[(k + 0) * W1T_PITCH + lane], __shfl_sync(0xffffffffu, x1, k + 0), q0);
        q1 = fmaf(w2t[(k + 1) * W1T_PITCH + lane], __shfl_sync(0xffffffffu, x1, k + 1), q1);
        q2 = fmaf(w2t[(k + 2) * W1T_PITCH + lane], __shfl_sync(0xffffffffu, x1, k + 2), q2);
        q3 = fmaf(w2t[(k + 3) * W1T_PITCH + lane], __shfl_sync(0xffffffffu, x1, k + 3), q3);
    }
#pragma unroll
    for (int k = 0; k < NH; k += 4) {
        q0 = fmaf(w2t[(NH + k + 0) * W1T_PITCH + lane], __shfl_sync(0xffffffffu, hv, k + 0), q0);
        q1 = fmaf(w2t[(NH + k + 1) * W1T_PITCH + lane], __shfl_sync(0xffffffffu, hv, k + 1), q1);
        q2 = fmaf(w2t[(NH + k + 2) * W1T_PITCH + lane], __shfl_sync(0xffffffffu, hv, k + 2), q2);
        q3 = fmaf(w2t[(NH + k + 3) * W1T_PITCH + lane], __shfl_sync(0xffffffffu, hv, k + 3), q3);
    }
    float x2 = b2s[lane] + ((q0 + q1) + (q2 + q3));
    x2 = x2 >= 0.f ? x2 : 0.01f * x2;

    float v = Wd[(size_t)n * 2 * NH + lane] * x2
            + Wd[(size_t)n * 2 * NH + NH + lane] * hv;
#pragma unroll
    for (int o = 16; o; o >>= 1) v += __shfl_xor_sync(0xffffffffu, v, o);
    if (lane == 0) out[(size_t)b * NN + n] = v + bd[n];
}

extern "C" void kernel_launch(void* const* d_in, const int* in_sizes, int n_in,
                              void* d_out, int out_size)
{
    (void)in_sizes; (void)n_in; (void)out_size;
    const float* x  = (const float*)d_in[0];
    const float* g  = (const float*)d_in[2];
    const float* Wu = (const float*)d_in[5];
    const float* bu = (const float*)d_in[6];
    const float* Wc = (const float*)d_in[7];
    const float* bc = (const float*)d_in[8];
    const float* h0 = (const float*)d_in[9];
    const float* W1 = (const float*)d_in[10];
    const float* b1 = (const float*)d_in[11];
    const float* W2 = (const float*)d_in[12];
    const float* b2 = (const float*)d_in[13];
    const float* Wd = (const float*)d_in[14];
    const float* bd = (const float*)d_in[15];
    float* out = (float*)d_out;

    xh_kernel<<<NB * 16, 256>>>(x);
    prep_kernel<<<16384, 256>>>(g, Wu, Wc);

    cudaFuncSetAttribute(gemm_gru_kernel,
                         cudaFuncAttributeMaxDynamicSharedMemorySize, SMEM_BYTES);
    dim3 grid(8, 16, NB);
    gemm_gru_kernel<<<grid, 256, SMEM_BYTES>>>(bu, bc, h0);

    head_kernel<<<(NB * NN) / 32, 1024>>>(W1, b1, W2, b2, Wd, bd, out);
}